// round 1
// baseline (speedup 1.0000x reference)
#include <cuda_runtime.h>
#include <cstdint>

#define NPIX 32768
#define D2 324
#define NSTATBLK 256

// ---------------- scratch (static device allocations, allowed) ----------------
__device__ float g_bufA[NPIX*D2];
__device__ float g_bufB[NPIX*D2];
__device__ float g_bufC[NPIX*D2];
__device__ float g_bufD[NPIX*D2];
__device__ float g_bufE[NPIX*D2];

__device__ float g_psum[NSTATBLK*D2];
__device__ float g_psq [NSTATBLK*D2];
__device__ float g_scale[12][D2];
__device__ float g_shift[12][D2];

// ---------------- f0: 8-channel 3x3 tensor conv (16x16 -> 18x18) ----------------
// grid (32 h, 32 b), 256 threads, full 32-w row per block.
// smem: sT[3*256*32] sM[32*288] sAcc[324*33] sU[2592] sV[2592]
__global__ void __launch_bounds__(256) f0_kernel(const float* __restrict__ x,
    const float* __restrict__ U0, const float* __restrict__ V0,
    const float* __restrict__ b0, float* __restrict__ out)
{
    extern __shared__ float sm[];
    float* sT   = sm;            // 24576
    float* sM   = sm + 24576;    // 9216
    float* sAcc = sm + 33792;    // 10692 (324 rows, pitch 33)
    float* sU   = sm + 44484;    // 2592
    float* sV   = sm + 47076;    // 2592
    const int t = threadIdx.x;
    const int h = blockIdx.x, b = blockIdx.y;

    for (int e = t; e < 324*33; e += 256) sAcc[e] = b0[e/33];

    for (int c = 0; c < 8; ++c) {
        for (int e = t; e < 2592; e += 256) { sU[e] = U0[c*2592+e]; sV[e] = V0[c*2592+e]; }
        const float* xc = x + (size_t)(b*8+c)*262144;
        for (int e = t; e < 24576; e += 256) {
            int rr = e >> 13, rem = e & 8191;
            int pq = rem >> 5, w = rem & 31;
            int hr = h - 1 + rr;
            sT[e] = (hr >= 0 && hr < 32) ? xc[(pq*32 + hr)*32 + w] : 0.f;
        }
        __syncthreads();
        for (int tap = 0; tap < 9; ++tap) {
            const int di = tap/3, dj = tap%3;
            const float* Ut = sU + tap*288;
            const float* Vt = sV + tap*288;
            const float* Tr = sT + di*8192;
            // phase1: M[a][qq][w] = sum_p U0[a,p] * T[p*16+qq][w+dj-1]
            for (int e = t; e < 9216; e += 256) {
                int aq = e >> 5, w = e & 31;
                int a = aq >> 4, qq = aq & 15;
                int iw = w + dj - 1;
                float m = 0.f;
                if ((unsigned)iw < 32u) {
                    const float* Up = Ut + a*16;
                    const float* Tp = Tr + qq*32 + iw;
                    float m0 = 0.f, m1 = 0.f;
                    #pragma unroll
                    for (int p = 0; p < 16; p += 2) {
                        m0 = fmaf(Up[p],   Tp[p*512],     m0);
                        m1 = fmaf(Up[p+1], Tp[(p+1)*512], m1);
                    }
                    m = m0 + m1;
                }
                sM[e] = m;
            }
            __syncthreads();
            // phase2: acc[a][d][w] += sum_qq M[a][qq][w] * V0[qq,d]
            for (int e = t; e < 10368; e += 256) {
                int ad = e >> 5, w = e & 31;
                int a = ad/18, d = ad - a*18;
                const float* Mp = sM + (a*16)*32 + w;
                const float* Vp = Vt + d;
                float s0 = 0.f, s1 = 0.f;
                #pragma unroll
                for (int qq = 0; qq < 16; qq += 2) {
                    s0 = fmaf(Mp[qq*32],     Vp[qq*18],     s0);
                    s1 = fmaf(Mp[(qq+1)*32], Vp[(qq+1)*18], s1);
                }
                sAcc[ad*33 + w] += s0 + s1;
            }
            __syncthreads();
        }
    }
    float* op = out + (size_t)((b*32+h)*32)*324;
    for (int e = t; e < 10368; e += 256) {
        int w = e / 324, ad = e - w*324;
        op[w*324 + ad] = sAcc[ad*33 + w];
    }
}

// ---------------- conv1x1: Y = U (BN/PReLU(X)) V + b ----------------
__global__ void __launch_bounds__(324) conv1x1_kernel(
    const float* __restrict__ in, int slot, const float* __restrict__ alpha_ptr,
    const float* __restrict__ U, const float* __restrict__ V,
    const float* __restrict__ bm, float* __restrict__ out)
{
    __shared__ float sU[324], sV[324], sB[324], sSc[324], sSh[324], sX[324], sM[324];
    const int t = threadIdx.x;
    sU[t] = U[t]; sV[t] = V[t]; sB[t] = bm[t];
    sSc[t] = (slot >= 0) ? g_scale[slot][t] : 1.f;
    sSh[t] = (slot >= 0) ? g_shift[slot][t] : 0.f;
    const float alpha = alpha_ptr ? *alpha_ptr : 1.f;
    __syncthreads();
    const int p = t/18, q = t - p*18;
    const int pix0 = blockIdx.x * 8;
    for (int k = 0; k < 8; ++k) {
        const size_t base = (size_t)(pix0 + k)*324;
        float v = in[base + t];
        v = fmaf(v, sSc[t], sSh[t]);
        if (v < 0.f) v *= alpha;
        sX[t] = v;
        __syncthreads();
        float m0 = 0.f, m1 = 0.f;
        #pragma unroll
        for (int j = 0; j < 18; j += 2) {
            m0 = fmaf(sX[p*18+j],   sV[j*18+q],     m0);
            m1 = fmaf(sX[p*18+j+1], sV[(j+1)*18+q], m1);
        }
        sM[t] = m0 + m1;
        __syncthreads();
        float y0 = 0.f, y1 = 0.f;
        #pragma unroll
        for (int j = 0; j < 18; j += 2) {
            y0 = fmaf(sU[p*18+j],   sM[j*18+q],     y0);
            y1 = fmaf(sU[p*18+j+1], sM[(j+1)*18+q], y1);
        }
        out[base + t] = y0 + y1 + sB[t];
        __syncthreads();
    }
}

// ---------------- conv3x3 ----------------
__global__ void __launch_bounds__(324) conv3x3_kernel(
    const float* __restrict__ in, int slot, const float* __restrict__ alpha_ptr,
    const float* __restrict__ U9, const float* __restrict__ V9,
    const float* __restrict__ bm, float* __restrict__ out)
{
    __shared__ float sU[2916], sV[2916], sB[324], sSc[324], sSh[324], sX[324], sM[324];
    const int t = threadIdx.x;
    for (int e = t; e < 2916; e += 324) { sU[e] = U9[e]; sV[e] = V9[e]; }
    sB[t] = bm[t];
    sSc[t] = g_scale[slot][t];
    sSh[t] = g_shift[slot][t];
    const float alpha = *alpha_ptr;
    __syncthreads();
    const int p = t/18, q = t - p*18;
    const int pix0 = blockIdx.x * 4;
    for (int k = 0; k < 4; ++k) {
        const int pix = pix0 + k;
        const int hw = pix & 1023;
        const int hh = hw >> 5, ww = hw & 31;
        float y = sB[t];
        for (int tap = 0; tap < 9; ++tap) {
            const int di = tap/3 - 1, dj = tap%3 - 1;
            const int nh = hh + di, nw = ww + dj;
            float v = 0.f;
            if ((unsigned)nh < 32u && (unsigned)nw < 32u) {
                v = in[(size_t)(pix + di*32 + dj)*324 + t];
                v = fmaf(v, sSc[t], sSh[t]);
                if (v < 0.f) v *= alpha;
            }
            sX[t] = v;
            __syncthreads();
            const float* Vt = sV + tap*324;
            float m0 = 0.f, m1 = 0.f;
            #pragma unroll
            for (int j = 0; j < 18; j += 2) {
                m0 = fmaf(sX[p*18+j],   Vt[j*18+q],     m0);
                m1 = fmaf(sX[p*18+j+1], Vt[(j+1)*18+q], m1);
            }
            sM[t] = m0 + m1;
            __syncthreads();
            const float* Ut = sU + tap*324;
            float y0 = 0.f, y1 = 0.f;
            #pragma unroll
            for (int j = 0; j < 18; j += 2) {
                y0 = fmaf(Ut[p*18+j],   sM[j*18+q],     y0);
                y1 = fmaf(Ut[p*18+j+1], sM[(j+1)*18+q], y1);
            }
            y += y0 + y1;
            __syncthreads();
        }
        out[(size_t)pix*324 + t] = y;
    }
}

// ---------------- BN stats: deterministic two-stage reduction ----------------
__global__ void __launch_bounds__(324) stats_kernel(const float* __restrict__ in) {
    const int t = threadIdx.x;
    const size_t base = (size_t)blockIdx.x * 128 * 324;
    float s = 0.f, ss = 0.f;
    for (int i = 0; i < 128; ++i) {
        float v = in[base + (size_t)i*324 + t];
        s += v; ss = fmaf(v, v, ss);
    }
    g_psum[blockIdx.x*324 + t] = s;
    g_psq [blockIdx.x*324 + t] = ss;
}

__global__ void __launch_bounds__(324) finalize_kernel(
    const float* __restrict__ gamma, const float* __restrict__ beta, int slot) {
    const int t = threadIdx.x;
    float s = 0.f, ss = 0.f;
    for (int i = 0; i < NSTATBLK; ++i) { s += g_psum[i*324 + t]; ss += g_psq[i*324 + t]; }
    const float mean = s * (1.f/32768.f);
    const float var  = ss * (1.f/32768.f) - mean*mean;
    const float inv  = rsqrtf(var + 1e-5f);
    const float sc   = gamma[t]*inv;
    g_scale[slot][t] = sc;
    g_shift[slot][t] = beta[t] - mean*sc;
}

// ---------------- residual combine: out = BN_a(a) + BN_b(b) ----------------
__global__ void __launch_bounds__(324) combine_kernel(
    const float* __restrict__ a, int slotA,
    const float* __restrict__ b, int slotB, float* __restrict__ out) {
    const int t = threadIdx.x;
    const float sA = g_scale[slotA][t], hA = g_shift[slotA][t];
    const float sB = g_scale[slotB][t], hB = g_shift[slotB][t];
    const size_t base = (size_t)blockIdx.x * 8 * 324;
    for (int k = 0; k < 8; ++k) {
        const size_t idx = base + (size_t)k*324 + t;
        out[idx] = fmaf(a[idx], sA, hA) + fmaf(b[idx], sB, hB);
    }
}

// ---------------- head: out[b,o,h,w] = <BN_a(a)+BN_b(b), Wf[o]> + bf[o] ----------------
__global__ void __launch_bounds__(324) head_kernel(
    const float* __restrict__ a, int slotA,
    const float* __restrict__ b, int slotB,
    const float* __restrict__ Wf, const float* __restrict__ bf,
    float* __restrict__ out) {
    __shared__ float sW[3240], sX[324], sPart[180];
    const int t = threadIdx.x;
    for (int e = t; e < 3240; e += 324) sW[e] = Wf[e];
    const float sA = g_scale[slotA][t], hA = g_shift[slotA][t];
    const float sB = g_scale[slotB][t], hB = g_shift[slotB][t];
    __syncthreads();
    const int pix0 = blockIdx.x * 8;
    for (int k = 0; k < 8; ++k) {
        const int pix = pix0 + k;
        const size_t base = (size_t)pix * 324;
        sX[t] = fmaf(a[base+t], sA, hA) + fmaf(b[base+t], sB, hB);
        __syncthreads();
        if (t < 180) {
            const int o = t/18, p = t - o*18;
            const float* xr = sX + p*18;
            const float* wr = sW + o*324 + p*18;
            float s = 0.f;
            #pragma unroll
            for (int j = 0; j < 18; ++j) s = fmaf(xr[j], wr[j], s);
            sPart[t] = s;
        }
        __syncthreads();
        if (t < 10) {
            float r = bf[t];
            #pragma unroll
            for (int p = 0; p < 18; ++p) r += sPart[t*18 + p];
            const int bb = pix >> 10, hw = pix & 1023;
            out[(size_t)(bb*10 + t)*1024 + hw] = r;
        }
        __syncthreads();
    }
}

// ---------------- host ----------------
static void run_stats(const float* buf, const float* gamma, const float* beta, int slot, int grow) {
    stats_kernel<<<NSTATBLK, 324>>>(buf);
    finalize_kernel<<<1, 324>>>(gamma + grow*324, beta + grow*324, slot);
}

extern "C" void kernel_launch(void* const* d_in, const int* in_sizes, int n_in,
                              void* d_out, int out_size) {
    (void)in_sizes; (void)n_in; (void)out_size;
    const float* x     = (const float*)d_in[0];
    const float* U0    = (const float*)d_in[1];
    const float* V0    = (const float*)d_in[2];
    const float* b0    = (const float*)d_in[3];
    const float* U1    = (const float*)d_in[4];
    const float* V1    = (const float*)d_in[5];
    const float* b1    = (const float*)d_in[6];
    const float* U3    = (const float*)d_in[7];
    const float* V3    = (const float*)d_in[8];
    const float* b3    = (const float*)d_in[9];
    const float* Wf    = (const float*)d_in[10];
    const float* bf    = (const float*)d_in[11];
    const float* gamma = (const float*)d_in[12];
    const float* beta  = (const float*)d_in[13];
    const float* alpha = (const float*)d_in[14];
    float* out = (float*)d_out;

    float *bufA, *bufB, *bufC, *bufD, *bufE;
    cudaGetSymbolAddress((void**)&bufA, g_bufA);
    cudaGetSymbolAddress((void**)&bufB, g_bufB);
    cudaGetSymbolAddress((void**)&bufC, g_bufC);
    cudaGetSymbolAddress((void**)&bufD, g_bufD);
    cudaGetSymbolAddress((void**)&bufE, g_bufE);

    const int F0_SMEM = 49668 * 4;
    cudaFuncSetAttribute(f0_kernel, cudaFuncAttributeMaxDynamicSharedMemorySize, F0_SMEM);

    // f0 -> h_raw (bufA), stats slot0 (gamma row 0)
    f0_kernel<<<dim3(32,32), 256, F0_SMEM>>>(x, U0, V0, b0, bufA);
    run_stats(bufA, gamma, beta, 0, 0);

    // ---- block 1 ----
    // s1 = conv1x1(h) raw -> bufB, slot1 (gamma 1)
    conv1x1_kernel<<<4096,324>>>(bufA, 0, alpha+0, U1+0*324, V1+0*324, b1+0*324, bufB);
    run_stats(bufB, gamma, beta, 1, 1);
    // t1 = conv1x1(h) raw -> bufD, slot2 (gamma 2)
    conv1x1_kernel<<<4096,324>>>(bufA, 0, alpha+0, U1+1*324, V1+1*324, b1+1*324, bufD);
    run_stats(bufD, gamma, beta, 2, 2);
    // t2 = conv3x3(prelu(bn(t1))) -> bufE, slot3 (gamma 3)
    conv3x3_kernel<<<8192,324>>>(bufD, 2, alpha+1, U3+0*2916, V3+0*2916, b3+0*324, bufE);
    run_stats(bufE, gamma, beta, 3, 3);
    // t3 = conv1x1(prelu(bn(t2))) -> bufD, slot4 (gamma 4)
    conv1x1_kernel<<<4096,324>>>(bufE, 3, alpha+2, U1+2*324, V1+2*324, b1+2*324, bufD);
    run_stats(bufD, gamma, beta, 4, 4);
    // x11 = bn(t3) + bn(s1) -> bufA
    combine_kernel<<<4096,324>>>(bufD, 4, bufB, 1, bufA);

    // ---- block 2 ----
    // s2 = conv1x1(x11) raw -> bufB, slot5 (gamma 5)  [kept alive for block 3!]
    conv1x1_kernel<<<4096,324>>>(bufA, -1, nullptr, U1+3*324, V1+3*324, b1+3*324, bufB);
    run_stats(bufB, gamma, beta, 5, 5);
    // t1 -> bufD, slot6 (gamma 6)
    conv1x1_kernel<<<4096,324>>>(bufA, -1, nullptr, U1+4*324, V1+4*324, b1+4*324, bufD);
    run_stats(bufD, gamma, beta, 6, 6);
    // t2 -> bufE, slot7 (gamma 7)
    conv3x3_kernel<<<8192,324>>>(bufD, 6, alpha+3, U3+1*2916, V3+1*2916, b3+1*324, bufE);
    run_stats(bufE, gamma, beta, 7, 7);
    // t3 -> bufD, slot8 (gamma 8)
    conv1x1_kernel<<<4096,324>>>(bufE, 7, alpha+4, U1+5*324, V1+5*324, b1+5*324, bufD);
    run_stats(bufD, gamma, beta, 8, 8);
    // x21 = bn(t3) + bn(s2) -> bufC
    combine_kernel<<<4096,324>>>(bufD, 8, bufB, 5, bufC);

    // ---- block 3 (bug-faithful: identity = bn(s2); the U1[6]/gamma[9] conv is unused -> skipped) ----
    // t1 -> bufD, slot9 (gamma 10)
    conv1x1_kernel<<<4096,324>>>(bufC, -1, nullptr, U1+7*324, V1+7*324, b1+7*324, bufD);
    run_stats(bufD, gamma, beta, 9, 10);
    // t2 -> bufE, slot10 (gamma 11)
    conv3x3_kernel<<<8192,324>>>(bufD, 9, alpha+5, U3+2*2916, V3+2*2916, b3+2*324, bufE);
    run_stats(bufE, gamma, beta, 10, 11);
    // t3 -> bufD, slot11 (gamma 12)
    conv1x1_kernel<<<4096,324>>>(bufE, 10, alpha+6, U1+8*324, V1+8*324, b1+8*324, bufD);
    run_stats(bufD, gamma, beta, 11, 12);

    // head: out = <bn(t3) + bn(s2), Wf> + bf
    head_kernel<<<4096,324>>>(bufD, 11, bufB, 5, Wf, bf, out);
}

// round 2
// speedup vs baseline: 2.3903x; 2.3903x over previous
#include <cuda_runtime.h>
#include <cstdint>

typedef unsigned long long u64;

#define NPIX 32768
#define NBLK 1024

// ---------------- scratch ----------------
__device__ float g_bufA[NPIX*324];
__device__ float g_bufB[NPIX*324];
__device__ float g_bufC[NPIX*324];
__device__ float g_bufD[NPIX*324];
__device__ float g_bufE[NPIX*324];

__device__ float g_psum[NBLK*324];
__device__ float g_psq [NBLK*324];
__device__ float g_scale[12][324];
__device__ float g_shift[12][324];

// ---------------- f32x2 helpers ----------------
__device__ __forceinline__ u64 pk2(float lo, float hi){ u64 r; asm("mov.b64 %0,{%1,%2};":"=l"(r):"f"(lo),"f"(hi)); return r; }
__device__ __forceinline__ u64 dup2(float v){ return pk2(v, v); }
__device__ __forceinline__ void fma2(u64 &d, u64 a, u64 b){ asm("fma.rn.f32x2 %0,%1,%2,%0;":"+l"(d):"l"(a),"l"(b)); }

// acc[0..8] += xd * row[0..8]   (row = 18 floats as 9 f32x2, 16B-aligned)
#define FMA9(acc, xd, vbase) { \
  const ulonglong2* _vv = (const ulonglong2*)(vbase); \
  ulonglong2 _a0=_vv[0], _a1=_vv[1], _a2=_vv[2], _a3=_vv[3]; \
  u64 _a8 = ((const u64*)(vbase))[8]; \
  fma2(acc[0],xd,_a0.x); fma2(acc[1],xd,_a0.y); \
  fma2(acc[2],xd,_a1.x); fma2(acc[3],xd,_a1.y); \
  fma2(acc[4],xd,_a2.x); fma2(acc[5],xd,_a2.y); \
  fma2(acc[6],xd,_a3.x); fma2(acc[7],xd,_a3.y); \
  fma2(acc[8],xd,_a8); }

#define ST9(dst, acc) { \
  ulonglong2* _dd=(ulonglong2*)(dst); \
  _dd[0]=make_ulonglong2(acc[0],acc[1]); _dd[1]=make_ulonglong2(acc[2],acc[3]); \
  _dd[2]=make_ulonglong2(acc[4],acc[5]); _dd[3]=make_ulonglong2(acc[6],acc[7]); \
  ((u64*)(dst))[8]=acc[8]; }

// ---------------- f0: 8-channel 3x3 tensor conv (16x16 -> 18x18) ----------------
// 576 threads = 32 pixels (one h-row) x 18 threads. grid (32 h, 32 b).
// smem: sT[3*256*33] sUt[9*288] sVp[9*320] sN[32*18*20]
__global__ void __launch_bounds__(576) f0_kernel(const float* __restrict__ x,
    const float* __restrict__ U0, const float* __restrict__ V0,
    const float* __restrict__ b0, float* __restrict__ out)
{
    extern __shared__ float sm[];
    float* sT  = sm;                 // 25344
    float* sUt = sm + 25344;         // 2592  [tap][p*18+a]
    float* sVp = sm + 27936;         // 2880  [tap][qq*20+d]
    float* sN  = sm + 30816;         // 11520 [pixl][row*20+d]
    const int t = threadIdx.x;
    const int j = t % 18, pixl = t / 18;
    const int h = blockIdx.x, b = blockIdx.y;

    u64 yacc[9];
    #pragma unroll
    for (int k = 0; k < 9; ++k) yacc[k] = *(const u64*)(b0 + j*18 + 2*k);

    for (int c = 0; c < 8; ++c) {
        __syncthreads();
        const float* xc = x + (size_t)(b*8 + c)*262144;
        for (int e = t; e < 24576; e += 576) {
            int rr = e >> 13, rem = e & 8191;
            int pq = rem >> 5, w = rem & 31;
            int hr = h - 1 + rr;
            int p = pq >> 4, qq = pq & 15;
            sT[rr*8448 + (qq*16 + p)*33 + w] = ((unsigned)hr < 32u) ? xc[pq*1024 + hr*32 + w] : 0.f;
        }
        const float* U0c = U0 + c*2592;   // [tap][a][p]
        const float* V0c = V0 + c*2592;   // [tap][qq][d]
        for (int e = t; e < 2592; e += 576) {
            int tap = e/288, r = e%288, a = r/16, p = r%16;
            sUt[tap*288 + p*18 + a] = U0c[e];
        }
        for (int e = t; e < 2880; e += 576) {
            int tap = e/320, r = e%320, qq = r/20, d = r%20;
            sVp[e] = (d < 18) ? V0c[(tap*16 + qq)*18 + d] : 0.f;
        }
        __syncthreads();

        for (int tap = 0; tap < 9; ++tap) {
            const int di = tap/3, dj = tap%3;
            const int iw = pixl + dj - 1;
            const bool valid = (unsigned)iw < 32u;
            if (valid && j < 16) {
                const float* Tb = sT + di*8448 + iw;
                u64 nacc[9];
                #pragma unroll
                for (int k = 0; k < 9; ++k) nacc[k] = 0ull;
                #pragma unroll
                for (int qq = 0; qq < 16; ++qq) {
                    u64 xd = dup2(Tb[(qq*16 + j)*33]);
                    FMA9(nacc, xd, sVp + tap*320 + qq*20);
                }
                ST9(sN + pixl*360 + j*20, nacc);
            }
            __syncthreads();
            if (valid) {
                #pragma unroll
                for (int p = 0; p < 16; ++p) {
                    u64 ud = dup2(sUt[tap*288 + p*18 + j]);
                    FMA9(yacc, ud, sN + pixl*360 + p*20);
                }
            }
            __syncthreads();
        }
    }
    const int bid = b*32 + h;
    const size_t obase = ((size_t)bid*32 + pixl)*324 + j*18;
    #pragma unroll
    for (int k = 0; k < 9; ++k) *(u64*)(out + obase + 2*k) = yacc[k];
    // stats staging + per-block partials
    ST9(sN + pixl*360 + j*20, yacc);
    __syncthreads();
    if (t < 324) {
        int a = t/18, d = t - a*18;
        float s = 0.f, ss = 0.f;
        #pragma unroll 4
        for (int pp = 0; pp < 32; ++pp) {
            float v = sN[pp*360 + a*20 + d];
            s += v; ss = fmaf(v, v, ss);
        }
        g_psum[bid*324 + t] = s;
        g_psq [bid*324 + t] = ss;
    }
}

// ---------------- conv1x1 ----------------
// 576 threads = 32 pixels x 18. grid 1024.
__global__ void __launch_bounds__(576) conv1x1_kernel(
    const float* __restrict__ in, int slot, const float* __restrict__ alpha_ptr,
    const float* __restrict__ U, const float* __restrict__ V,
    const float* __restrict__ bm, float* __restrict__ out)
{
    extern __shared__ float sm[];
    float* sV  = sm;          // 360  [q*20+d]
    float* sUt = sm + 360;    // 324  [p*18+a]
    float* sBp = sm + 684;    // 360
    float* sSc = sm + 1044;   // 324
    float* sSh = sm + 1368;   // 324
    float* sN  = sm + 1692;   // 11520
    const int t = threadIdx.x;
    const int j = t % 18, pixl = t / 18;

    if (t < 360) { int q = t/20, d = t%20;
        sV[t]  = (d < 18) ? V[q*18 + d]  : 0.f;
        sBp[t] = (d < 18) ? bm[q*18 + d] : 0.f; }
    for (int e = t; e < 324; e += 576) {
        sUt[(e%18)*18 + e/18] = U[e];
        sSc[e] = (slot >= 0) ? g_scale[slot][e] : 1.f;
        sSh[e] = (slot >= 0) ? g_shift[slot][e] : 0.f;
    }
    const float alpha = (slot >= 0 && alpha_ptr) ? *alpha_ptr : 1.f;
    __syncthreads();

    const size_t base = ((size_t)blockIdx.x*32 + pixl)*324 + j*18;
    float xr[18];
    #pragma unroll
    for (int q = 0; q < 9; ++q) {
        float2 v  = *(const float2*)(in + base + 2*q);
        float2 sc = *(const float2*)(sSc + j*18 + 2*q);
        float2 sh = *(const float2*)(sSh + j*18 + 2*q);
        float a0 = fmaf(v.x, sc.x, sh.x); if (a0 < 0.f) a0 *= alpha;
        float a1 = fmaf(v.y, sc.y, sh.y); if (a1 < 0.f) a1 *= alpha;
        xr[2*q] = a0; xr[2*q+1] = a1;
    }
    u64 nacc[9];
    #pragma unroll
    for (int k = 0; k < 9; ++k) nacc[k] = 0ull;
    #pragma unroll
    for (int q = 0; q < 18; ++q) {
        u64 xd = dup2(xr[q]);
        FMA9(nacc, xd, sV + q*20);
    }
    ST9(sN + pixl*360 + j*20, nacc);
    __syncthreads();

    u64 yacc[9];
    {
        const ulonglong2* bb = (const ulonglong2*)(sBp + j*20);
        ulonglong2 b0_ = bb[0], b1_ = bb[1], b2_ = bb[2], b3_ = bb[3];
        yacc[0]=b0_.x; yacc[1]=b0_.y; yacc[2]=b1_.x; yacc[3]=b1_.y;
        yacc[4]=b2_.x; yacc[5]=b2_.y; yacc[6]=b3_.x; yacc[7]=b3_.y;
        yacc[8]=((const u64*)(sBp + j*20))[8];
    }
    #pragma unroll
    for (int p = 0; p < 18; ++p) {
        u64 ud = dup2(sUt[p*18 + j]);
        FMA9(yacc, ud, sN + pixl*360 + p*20);
    }
    #pragma unroll
    for (int k = 0; k < 9; ++k) *(u64*)(out + base + 2*k) = yacc[k];
    __syncthreads();
    ST9(sN + pixl*360 + j*20, yacc);
    __syncthreads();
    if (t < 324) {
        int a = t/18, d = t - a*18;
        float s = 0.f, ss = 0.f;
        #pragma unroll 4
        for (int pp = 0; pp < 32; ++pp) {
            float v = sN[pp*360 + a*20 + d];
            s += v; ss = fmaf(v, v, ss);
        }
        g_psum[blockIdx.x*324 + t] = s;
        g_psq [blockIdx.x*324 + t] = ss;
    }
}

// ---------------- conv3x3 ----------------
__global__ void __launch_bounds__(576) conv3x3_kernel(
    const float* __restrict__ in, int slot, const float* __restrict__ alpha_ptr,
    const float* __restrict__ U9, const float* __restrict__ V9,
    const float* __restrict__ bm, float* __restrict__ out)
{
    extern __shared__ float sm[];
    float* sV  = sm;           // 3240 [tap][q*20+d]
    float* sUt = sm + 3240;    // 2916 [tap][p*18+a]
    float* sBp = sm + 6156;    // 360
    float* sSc = sm + 6516;    // 324
    float* sSh = sm + 6840;    // 324
    float* sN  = sm + 7164;    // 11520
    const int t = threadIdx.x;
    const int j = t % 18, pixl = t / 18;

    for (int e = t; e < 3240; e += 576) {
        int tap = e/360, r = e%360, q = r/20, d = r%20;
        sV[e] = (d < 18) ? V9[(tap*18 + q)*18 + d] : 0.f;
    }
    for (int e = t; e < 2916; e += 576) {
        int tap = e/324, r = e%324, a = r/18, p = r%18;
        sUt[tap*324 + p*18 + a] = U9[e];
    }
    if (t < 360) { int q = t/20, d = t%20; sBp[t] = (d < 18) ? bm[q*18 + d] : 0.f; }
    for (int e = t; e < 324; e += 576) { sSc[e] = g_scale[slot][e]; sSh[e] = g_shift[slot][e]; }
    const float alpha = *alpha_ptr;
    __syncthreads();

    const int pix = blockIdx.x*32 + pixl;
    const int hw = pix & 1023, hh = hw >> 5, ww = hw & 31;
    u64 yacc[9];
    {
        const ulonglong2* bb = (const ulonglong2*)(sBp + j*20);
        ulonglong2 b0_ = bb[0], b1_ = bb[1], b2_ = bb[2], b3_ = bb[3];
        yacc[0]=b0_.x; yacc[1]=b0_.y; yacc[2]=b1_.x; yacc[3]=b1_.y;
        yacc[4]=b2_.x; yacc[5]=b2_.y; yacc[6]=b3_.x; yacc[7]=b3_.y;
        yacc[8]=((const u64*)(sBp + j*20))[8];
    }

    for (int tap = 0; tap < 9; ++tap) {
        const int di = tap/3 - 1, dj = tap%3 - 1;
        const bool valid = ((unsigned)(hh + di) < 32u) && ((unsigned)(ww + dj) < 32u);
        if (valid) {
            const float* xin = in + ((size_t)pix + di*32 + dj)*324 + j*18;
            u64 nacc[9];
            #pragma unroll
            for (int k = 0; k < 9; ++k) nacc[k] = 0ull;
            float xr[18];
            #pragma unroll
            for (int q = 0; q < 9; ++q) {
                float2 v  = *(const float2*)(xin + 2*q);
                float2 sc = *(const float2*)(sSc + j*18 + 2*q);
                float2 sh = *(const float2*)(sSh + j*18 + 2*q);
                float a0 = fmaf(v.x, sc.x, sh.x); if (a0 < 0.f) a0 *= alpha;
                float a1 = fmaf(v.y, sc.y, sh.y); if (a1 < 0.f) a1 *= alpha;
                xr[2*q] = a0; xr[2*q+1] = a1;
            }
            #pragma unroll
            for (int q = 0; q < 18; ++q) {
                u64 xd = dup2(xr[q]);
                FMA9(nacc, xd, sV + tap*360 + q*20);
            }
            ST9(sN + pixl*360 + j*20, nacc);
        }
        __syncthreads();
        if (valid) {
            #pragma unroll
            for (int p = 0; p < 18; ++p) {
                u64 ud = dup2(sUt[tap*324 + p*18 + j]);
                FMA9(yacc, ud, sN + pixl*360 + p*20);
            }
        }
        __syncthreads();
    }
    const size_t base = (size_t)pix*324 + j*18;
    #pragma unroll
    for (int k = 0; k < 9; ++k) *(u64*)(out + base + 2*k) = yacc[k];
    ST9(sN + pixl*360 + j*20, yacc);
    __syncthreads();
    if (t < 324) {
        int a = t/18, d = t - a*18;
        float s = 0.f, ss = 0.f;
        #pragma unroll 4
        for (int pp = 0; pp < 32; ++pp) {
            float v = sN[pp*360 + a*20 + d];
            s += v; ss = fmaf(v, v, ss);
        }
        g_psum[blockIdx.x*324 + t] = s;
        g_psq [blockIdx.x*324 + t] = ss;
    }
}

// ---------------- finalize: reduce per-block partials, fold BN affine ----------------
__global__ void __launch_bounds__(128) finalize_kernel(
    const float* __restrict__ gamma, const float* __restrict__ beta, int slot) {
    __shared__ float sh[128], sh2[128];
    const int pos = blockIdx.x, t = threadIdx.x;
    float s = 0.f, ss = 0.f;
    for (int i = t; i < NBLK; i += 128) { s += g_psum[i*324 + pos]; ss += g_psq[i*324 + pos]; }
    sh[t] = s; sh2[t] = ss; __syncthreads();
    for (int k = 64; k > 0; k >>= 1) {
        if (t < k) { sh[t] += sh[t+k]; sh2[t] += sh2[t+k]; }
        __syncthreads();
    }
    if (t == 0) {
        float mean = sh[0] * (1.f/32768.f);
        float var  = sh2[0] * (1.f/32768.f) - mean*mean;
        float inv  = rsqrtf(var + 1e-5f);
        float sc   = gamma[pos]*inv;
        g_scale[slot][pos] = sc;
        g_shift[slot][pos] = beta[pos] - mean*sc;
    }
}

// ---------------- residual combine ----------------
__global__ void __launch_bounds__(324) combine_kernel(
    const float* __restrict__ a, int slotA,
    const float* __restrict__ b, int slotB, float* __restrict__ out) {
    const int t = threadIdx.x;
    const float sA = g_scale[slotA][t], hA = g_shift[slotA][t];
    const float sB = g_scale[slotB][t], hB = g_shift[slotB][t];
    const size_t base = (size_t)blockIdx.x * 8 * 324;
    for (int k = 0; k < 8; ++k) {
        const size_t idx = base + (size_t)k*324 + t;
        out[idx] = fmaf(a[idx], sA, hA) + fmaf(b[idx], sB, hB);
    }
}

// ---------------- head ----------------
__global__ void __launch_bounds__(324) head_kernel(
    const float* __restrict__ a, int slotA,
    const float* __restrict__ b, int slotB,
    const float* __restrict__ Wf, const float* __restrict__ bf,
    float* __restrict__ out) {
    __shared__ float sW[3240], sX[324], sPart[180];
    const int t = threadIdx.x;
    for (int e = t; e < 3240; e += 324) sW[e] = Wf[e];
    const float sA = g_scale[slotA][t], hA = g_shift[slotA][t];
    const float sB = g_scale[slotB][t], hB = g_shift[slotB][t];
    __syncthreads();
    const int pix0 = blockIdx.x * 8;
    for (int k = 0; k < 8; ++k) {
        const int pix = pix0 + k;
        const size_t base = (size_t)pix * 324;
        sX[t] = fmaf(a[base+t], sA, hA) + fmaf(b[base+t], sB, hB);
        __syncthreads();
        if (t < 180) {
            const int o = t/18, p = t - o*18;
            const float* xr = sX + p*18;
            const float* wr = sW + o*324 + p*18;
            float s = 0.f;
            #pragma unroll
            for (int q = 0; q < 18; ++q) s = fmaf(xr[q], wr[q], s);
            sPart[t] = s;
        }
        __syncthreads();
        if (t < 10) {
            float r = bf[t];
            #pragma unroll
            for (int p = 0; p < 18; ++p) r += sPart[t*18 + p];
            const int bb = pix >> 10, hw = pix & 1023;
            out[(size_t)(bb*10 + t)*1024 + hw] = r;
        }
        __syncthreads();
    }
}

// ---------------- host ----------------
extern "C" void kernel_launch(void* const* d_in, const int* in_sizes, int n_in,
                              void* d_out, int out_size) {
    (void)in_sizes; (void)n_in; (void)out_size;
    const float* x     = (const float*)d_in[0];
    const float* U0    = (const float*)d_in[1];
    const float* V0    = (const float*)d_in[2];
    const float* b0    = (const float*)d_in[3];
    const float* U1    = (const float*)d_in[4];
    const float* V1    = (const float*)d_in[5];
    const float* b1    = (const float*)d_in[6];
    const float* U3    = (const float*)d_in[7];
    const float* V3    = (const float*)d_in[8];
    const float* b3    = (const float*)d_in[9];
    const float* Wf    = (const float*)d_in[10];
    const float* bf    = (const float*)d_in[11];
    const float* gamma = (const float*)d_in[12];
    const float* beta  = (const float*)d_in[13];
    const float* alpha = (const float*)d_in[14];
    float* out = (float*)d_out;

    float *bufA, *bufB, *bufC, *bufD, *bufE;
    cudaGetSymbolAddress((void**)&bufA, g_bufA);
    cudaGetSymbolAddress((void**)&bufB, g_bufB);
    cudaGetSymbolAddress((void**)&bufC, g_bufC);
    cudaGetSymbolAddress((void**)&bufD, g_bufD);
    cudaGetSymbolAddress((void**)&bufE, g_bufE);

    const int F0_SMEM = 42336 * 4;   // 169344 B
    const int C1_SMEM = 13212 * 4;   // 52848 B
    const int C3_SMEM = 18684 * 4;   // 74736 B
    cudaFuncSetAttribute(f0_kernel,      cudaFuncAttributeMaxDynamicSharedMemorySize, F0_SMEM);
    cudaFuncSetAttribute(conv1x1_kernel, cudaFuncAttributeMaxDynamicSharedMemorySize, C1_SMEM);
    cudaFuncSetAttribute(conv3x3_kernel, cudaFuncAttributeMaxDynamicSharedMemorySize, C3_SMEM);

    #define FIN(slot, grow) finalize_kernel<<<324,128>>>(gamma + (grow)*324, beta + (grow)*324, (slot))

    // f0
    f0_kernel<<<dim3(32,32), 576, F0_SMEM>>>(x, U0, V0, b0, bufA);
    FIN(0, 0);

    // ---- block 1 ----
    conv1x1_kernel<<<1024,576,C1_SMEM>>>(bufA, 0, alpha+0, U1+0*324, V1+0*324, b1+0*324, bufB);
    FIN(1, 1);
    conv1x1_kernel<<<1024,576,C1_SMEM>>>(bufA, 0, alpha+0, U1+1*324, V1+1*324, b1+1*324, bufD);
    FIN(2, 2);
    conv3x3_kernel<<<1024,576,C3_SMEM>>>(bufD, 2, alpha+1, U3+0*2916, V3+0*2916, b3+0*324, bufE);
    FIN(3, 3);
    conv1x1_kernel<<<1024,576,C1_SMEM>>>(bufE, 3, alpha+2, U1+2*324, V1+2*324, b1+2*324, bufD);
    FIN(4, 4);
    combine_kernel<<<4096,324>>>(bufD, 4, bufB, 1, bufA);

    // ---- block 2 ----
    conv1x1_kernel<<<1024,576,C1_SMEM>>>(bufA, -1, nullptr, U1+3*324, V1+3*324, b1+3*324, bufB);
    FIN(5, 5);
    conv1x1_kernel<<<1024,576,C1_SMEM>>>(bufA, -1, nullptr, U1+4*324, V1+4*324, b1+4*324, bufD);
    FIN(6, 6);
    conv3x3_kernel<<<1024,576,C3_SMEM>>>(bufD, 6, alpha+3, U3+1*2916, V3+1*2916, b3+1*324, bufE);
    FIN(7, 7);
    conv1x1_kernel<<<1024,576,C1_SMEM>>>(bufE, 7, alpha+4, U1+5*324, V1+5*324, b1+5*324, bufD);
    FIN(8, 8);
    combine_kernel<<<4096,324>>>(bufD, 8, bufB, 5, bufC);

    // ---- block 3 (bug-faithful: identity = bn(s2); U1[6]/gamma[9] conv unused) ----
    conv1x1_kernel<<<1024,576,C1_SMEM>>>(bufC, -1, nullptr, U1+7*324, V1+7*324, b1+7*324, bufD);
    FIN(9, 10);
    conv3x3_kernel<<<1024,576,C3_SMEM>>>(bufD, 9, alpha+5, U3+2*2916, V3+2*2916, b3+2*324, bufE);
    FIN(10, 11);
    conv1x1_kernel<<<1024,576,C1_SMEM>>>(bufE, 10, alpha+6, U1+8*324, V1+8*324, b1+8*324, bufD);
    FIN(11, 12);

    head_kernel<<<4096,324>>>(bufD, 11, bufB, 5, Wf, bf, out);
}